// round 9
// baseline (speedup 1.0000x reference)
#include <cuda_runtime.h>
#include <cuda_bf16.h>

// ---------------------------------------------------------------------------
// ENGNLayer: LayerNorm -> edge MLP (gather) -> scatter-mean -> node MLP + res
// N=40000 nodes, E=640000 edges, D=128. Pure fp32 baseline, block-tiled GEMMs.
// ---------------------------------------------------------------------------

#define N_NODES 40000
#define N_EDGES 640000
#define D 128
#define LN_EPS 1e-5f

// Scratch (allocation-free rule: device globals)
__device__ float g_h[N_NODES * D];      // LayerNorm output
__device__ float g_msum[N_NODES * D];   // scatter sum
__device__ float g_cnt[N_NODES];        // scatter count

__device__ __forceinline__ float silu(float x) {
    return x / (1.0f + __expf(-x));
}

// ---------------------------------------------------------------------------
// Kernel 1: LayerNorm over feature dim + zero the scatter buffers.
// 1 warp per node, 8 nodes per 256-thread block. 5000 blocks.
// ---------------------------------------------------------------------------
__global__ __launch_bounds__(256) void ln_kernel(
    const float* __restrict__ nf,
    const float* __restrict__ gamma,
    const float* __restrict__ beta)
{
    int node = blockIdx.x * 8 + (threadIdx.x >> 5);
    int lane = threadIdx.x & 31;
    if (node >= N_NODES) return;

    const float4* row = (const float4*)(nf + (size_t)node * D);
    float4 v = row[lane];

    float s  = v.x + v.y + v.z + v.w;
    float sq = v.x * v.x + v.y * v.y + v.z * v.z + v.w * v.w;
    #pragma unroll
    for (int off = 16; off; off >>= 1) {
        s  += __shfl_xor_sync(0xFFFFFFFFu, s, off);
        sq += __shfl_xor_sync(0xFFFFFFFFu, sq, off);
    }
    float mu   = s * (1.0f / D);
    float var  = sq * (1.0f / D) - mu * mu;
    float rstd = rsqrtf(var + LN_EPS);

    float4 g = ((const float4*)gamma)[lane];
    float4 b = ((const float4*)beta)[lane];
    float4 h;
    h.x = (v.x - mu) * rstd * g.x + b.x;
    h.y = (v.y - mu) * rstd * g.y + b.y;
    h.z = (v.z - mu) * rstd * g.z + b.z;
    h.w = (v.w - mu) * rstd * g.w + b.w;

    ((float4*)(g_h + (size_t)node * D))[lane] = h;
    float4 z = make_float4(0.f, 0.f, 0.f, 0.f);
    ((float4*)(g_msum + (size_t)node * D))[lane] = z;
    if (lane == 0) g_cnt[node] = 0.0f;
}

// ---------------------------------------------------------------------------
// Kernel 2: edge message MLP + scatter.
//   m1 = silu(concat(h[src], h[dst], ef) @ W1 + b1)   [64 x 384] x [384 x 128]
//   m2 = silu(m1 @ W2 + b2)                            [64 x 128] x [128 x 128]
//   red.add m2 into g_msum[src], count into g_cnt[src]
// 64 edges/block, 256 threads, 8x4 register microtile. 10000 blocks.
// Dynamic smem: As(8K) Bs(16K) Ms(32K) + idx/bias ~ 58.9 KB
// ---------------------------------------------------------------------------
#define EDGE_SMEM (8192 + 16384 + 32768 + 256 + 256 + 512 + 512)

__global__ __launch_bounds__(256, 3) void edge_kernel(
    const float* __restrict__ ef,
    const float* __restrict__ w1,  // [384,128]
    const float* __restrict__ b1,
    const float* __restrict__ w2,  // [128,128]
    const float* __restrict__ b2,
    const int*  __restrict__ src,
    const int*  __restrict__ dst)
{
    extern __shared__ char smem_raw[];
    float* As   = (float*)smem_raw;                      // [64][32]
    float* Bs   = (float*)(smem_raw + 8192);             // [32][128]
    float* Ms   = (float*)(smem_raw + 8192 + 16384);     // [64][128]
    float* s_b1 = (float*)(smem_raw + 8192 + 16384 + 32768);
    float* s_b2 = s_b1 + 128;
    int*   s_src = (int*)(s_b2 + 128);
    int*   s_dst = s_src + 64;

    const int tid = threadIdx.x;
    const int e0  = blockIdx.x * 64;

    if (tid < 64)  { s_src[tid] = src[e0 + tid]; s_dst[tid] = dst[e0 + tid]; }
    if (tid < 128) s_b1[tid] = b1[tid];
    else if (tid < 256) s_b2[tid - 128] = b2[tid - 128];
    __syncthreads();

    const int tx = tid & 31;            // column group: 32 groups of 4 cols
    const int ty = tid >> 5;            // row group:     8 groups of 8 rows
    const int row0 = ty * 8;
    const int col0 = tx * 4;

    const int arow = tid >> 2;          // A-load: row 0..63
    const int acol = (tid & 3) * 8;     // A-load: 8 consecutive k

    float acc[8][4];
    #pragma unroll
    for (int i = 0; i < 8; i++)
        #pragma unroll
        for (int j = 0; j < 4; j++) acc[i][j] = 0.0f;

    // ---- GEMM1: [64 x 384] @ [384 x 128], 12 k-tiles of 32 ----
    for (int kt = 0; kt < 12; ++kt) {
        int seg = kt >> 2;              // 0: h[src], 1: h[dst], 2: edge feats
        int kin = (kt & 3) * 32;

        const float* abase;
        if (seg == 0)      abase = g_h + (size_t)s_src[arow] * D;
        else if (seg == 1) abase = g_h + (size_t)s_dst[arow] * D;
        else               abase = ef  + (size_t)(e0 + arow) * D;

        float4 va = *(const float4*)(abase + kin + acol);
        float4 vb = *(const float4*)(abase + kin + acol + 4);
        *(float4*)(As + arow * 32 + acol)     = va;
        *(float4*)(As + arow * 32 + acol + 4) = vb;

        const float* wbase = w1 + kt * 32 * 128;
        #pragma unroll
        for (int i = 0; i < 4; i++) {
            int idx = (tid + i * 256) * 4;
            *(float4*)(Bs + idx) = *(const float4*)(wbase + idx);
        }
        __syncthreads();

        #pragma unroll
        for (int k = 0; k < 32; k++) {
            float4 bvec = *(const float4*)(Bs + k * 128 + col0);
            float a[8];
            #pragma unroll
            for (int i = 0; i < 8; i++) a[i] = As[(row0 + i) * 32 + k];
            #pragma unroll
            for (int i = 0; i < 8; i++) {
                acc[i][0] += a[i] * bvec.x;
                acc[i][1] += a[i] * bvec.y;
                acc[i][2] += a[i] * bvec.z;
                acc[i][3] += a[i] * bvec.w;
            }
        }
        __syncthreads();
    }

    // ---- bias + silu -> Ms ----
    {
        float bx = s_b1[col0], by = s_b1[col0 + 1], bz = s_b1[col0 + 2], bw = s_b1[col0 + 3];
        #pragma unroll
        for (int i = 0; i < 8; i++) {
            float4 v;
            v.x = silu(acc[i][0] + bx);
            v.y = silu(acc[i][1] + by);
            v.z = silu(acc[i][2] + bz);
            v.w = silu(acc[i][3] + bw);
            *(float4*)(Ms + (row0 + i) * 128 + col0) = v;
            acc[i][0] = 0.f; acc[i][1] = 0.f; acc[i][2] = 0.f; acc[i][3] = 0.f;
        }
    }
    __syncthreads();

    // ---- GEMM2: [64 x 128] @ [128 x 128], 4 k-tiles of 32 ----
    for (int kt = 0; kt < 4; ++kt) {
        const float* wbase = w2 + kt * 32 * 128;
        #pragma unroll
        for (int i = 0; i < 4; i++) {
            int idx = (tid + i * 256) * 4;
            *(float4*)(Bs + idx) = *(const float4*)(wbase + idx);
        }
        __syncthreads();

        #pragma unroll
        for (int k = 0; k < 32; k++) {
            int kk = kt * 32 + k;
            float4 bvec = *(const float4*)(Bs + k * 128 + col0);
            float a[8];
            #pragma unroll
            for (int i = 0; i < 8; i++) a[i] = Ms[(row0 + i) * 128 + kk];
            #pragma unroll
            for (int i = 0; i < 8; i++) {
                acc[i][0] += a[i] * bvec.x;
                acc[i][1] += a[i] * bvec.y;
                acc[i][2] += a[i] * bvec.z;
                acc[i][3] += a[i] * bvec.w;
            }
        }
        __syncthreads();
    }

    // ---- bias + silu + vectorized scatter (red.global.add.v4.f32) ----
    {
        float bx = s_b2[col0], by = s_b2[col0 + 1], bz = s_b2[col0 + 2], bw = s_b2[col0 + 3];
        #pragma unroll
        for (int i = 0; i < 8; i++) {
            int r = row0 + i;
            float vx = silu(acc[i][0] + bx);
            float vy = silu(acc[i][1] + by);
            float vz = silu(acc[i][2] + bz);
            float vw = silu(acc[i][3] + bw);
            float* dstp = g_msum + (size_t)s_src[r] * D + col0;
            asm volatile("red.global.add.v4.f32 [%0], {%1,%2,%3,%4};"
                         :: "l"(dstp), "f"(vx), "f"(vy), "f"(vz), "f"(vw)
                         : "memory");
        }
        if (tx == 0) {
            #pragma unroll
            for (int i = 0; i < 8; i++)
                atomicAdd(&g_cnt[s_src[row0 + i]], 1.0f);
        }
    }
}

// ---------------------------------------------------------------------------
// Kernel 3: node aggregation MLP + residual.
//   a = silu(concat(h, msum/cnt) @ AW1 + ab1); a = silu(a @ AW2 + ab2)
//   out = node_features + a
// 64 nodes/block, 256 threads. 625 blocks.
// ---------------------------------------------------------------------------
#define NODE_SMEM (8192 + 16384 + 32768 + 256 + 512 + 512)

__global__ __launch_bounds__(256, 3) void node_kernel(
    const float* __restrict__ nf,
    const float* __restrict__ w1,  // [256,128]
    const float* __restrict__ b1,
    const float* __restrict__ w2,  // [128,128]
    const float* __restrict__ b2,
    float* __restrict__ out)
{
    extern __shared__ char smem_raw[];
    float* As    = (float*)smem_raw;
    float* Bs    = (float*)(smem_raw + 8192);
    float* Ms    = (float*)(smem_raw + 8192 + 16384);
    float* s_inv = (float*)(smem_raw + 8192 + 16384 + 32768);
    float* s_b1  = s_inv + 64;
    float* s_b2  = s_b1 + 128;

    const int tid = threadIdx.x;
    const int n0  = blockIdx.x * 64;

    if (tid < 64) {
        float c = g_cnt[n0 + tid];
        s_inv[tid] = 1.0f / fmaxf(c, 1.0f);
    }
    if (tid < 128) s_b1[tid] = b1[tid];
    else if (tid < 256) s_b2[tid - 128] = b2[tid - 128];
    __syncthreads();

    const int tx = tid & 31;
    const int ty = tid >> 5;
    const int row0 = ty * 8;
    const int col0 = tx * 4;

    const int arow = tid >> 2;
    const int acol = (tid & 3) * 8;

    float acc[8][4];
    #pragma unroll
    for (int i = 0; i < 8; i++)
        #pragma unroll
        for (int j = 0; j < 4; j++) acc[i][j] = 0.0f;

    // ---- GEMM1: [64 x 256] @ [256 x 128], 8 k-tiles ----
    for (int kt = 0; kt < 8; ++kt) {
        int seg = kt >> 2;              // 0: h, 1: mean
        int kin = (kt & 3) * 32;

        const float* abase = (seg == 0 ? g_h : g_msum) + (size_t)(n0 + arow) * D;
        float4 va = *(const float4*)(abase + kin + acol);
        float4 vb = *(const float4*)(abase + kin + acol + 4);
        if (seg == 1) {
            float inv = s_inv[arow];
            va.x *= inv; va.y *= inv; va.z *= inv; va.w *= inv;
            vb.x *= inv; vb.y *= inv; vb.z *= inv; vb.w *= inv;
        }
        *(float4*)(As + arow * 32 + acol)     = va;
        *(float4*)(As + arow * 32 + acol + 4) = vb;

        const float* wbase = w1 + kt * 32 * 128;
        #pragma unroll
        for (int i = 0; i < 4; i++) {
            int idx = (tid + i * 256) * 4;
            *(float4*)(Bs + idx) = *(const float4*)(wbase + idx);
        }
        __syncthreads();

        #pragma unroll
        for (int k = 0; k < 32; k++) {
            float4 bvec = *(const float4*)(Bs + k * 128 + col0);
            float a[8];
            #pragma unroll
            for (int i = 0; i < 8; i++) a[i] = As[(row0 + i) * 32 + k];
            #pragma unroll
            for (int i = 0; i < 8; i++) {
                acc[i][0] += a[i] * bvec.x;
                acc[i][1] += a[i] * bvec.y;
                acc[i][2] += a[i] * bvec.z;
                acc[i][3] += a[i] * bvec.w;
            }
        }
        __syncthreads();
    }

    {
        float bx = s_b1[col0], by = s_b1[col0 + 1], bz = s_b1[col0 + 2], bw = s_b1[col0 + 3];
        #pragma unroll
        for (int i = 0; i < 8; i++) {
            float4 v;
            v.x = silu(acc[i][0] + bx);
            v.y = silu(acc[i][1] + by);
            v.z = silu(acc[i][2] + bz);
            v.w = silu(acc[i][3] + bw);
            *(float4*)(Ms + (row0 + i) * 128 + col0) = v;
            acc[i][0] = 0.f; acc[i][1] = 0.f; acc[i][2] = 0.f; acc[i][3] = 0.f;
        }
    }
    __syncthreads();

    // ---- GEMM2: [64 x 128] @ [128 x 128] ----
    for (int kt = 0; kt < 4; ++kt) {
        const float* wbase = w2 + kt * 32 * 128;
        #pragma unroll
        for (int i = 0; i < 4; i++) {
            int idx = (tid + i * 256) * 4;
            *(float4*)(Bs + idx) = *(const float4*)(wbase + idx);
        }
        __syncthreads();

        #pragma unroll
        for (int k = 0; k < 32; k++) {
            int kk = kt * 32 + k;
            float4 bvec = *(const float4*)(Bs + k * 128 + col0);
            float a[8];
            #pragma unroll
            for (int i = 0; i < 8; i++) a[i] = Ms[(row0 + i) * 128 + kk];
            #pragma unroll
            for (int i = 0; i < 8; i++) {
                acc[i][0] += a[i] * bvec.x;
                acc[i][1] += a[i] * bvec.y;
                acc[i][2] += a[i] * bvec.z;
                acc[i][3] += a[i] * bvec.w;
            }
        }
        __syncthreads();
    }

    // ---- bias + silu + residual -> out ----
    {
        float bx = s_b2[col0], by = s_b2[col0 + 1], bz = s_b2[col0 + 2], bw = s_b2[col0 + 3];
        #pragma unroll
        for (int i = 0; i < 8; i++) {
            int node = n0 + row0 + i;
            float4 res = *(const float4*)(nf + (size_t)node * D + col0);
            float4 v;
            v.x = res.x + silu(acc[i][0] + bx);
            v.y = res.y + silu(acc[i][1] + by);
            v.z = res.z + silu(acc[i][2] + bz);
            v.w = res.w + silu(acc[i][3] + bw);
            *(float4*)(out + (size_t)node * D + col0) = v;
        }
    }
}

// ---------------------------------------------------------------------------
extern "C" void kernel_launch(void* const* d_in, const int* in_sizes, int n_in,
                              void* d_out, int out_size)
{
    const float* nf    = (const float*)d_in[0];
    const float* ef    = (const float*)d_in[1];
    const float* gamma = (const float*)d_in[2];
    const float* beta  = (const float*)d_in[3];
    const float* mw1   = (const float*)d_in[4];
    const float* mb1   = (const float*)d_in[5];
    const float* mw2   = (const float*)d_in[6];
    const float* mb2   = (const float*)d_in[7];
    const float* aw1   = (const float*)d_in[8];
    const float* ab1   = (const float*)d_in[9];
    const float* aw2   = (const float*)d_in[10];
    const float* ab2   = (const float*)d_in[11];
    const int*   eidx  = (const int*)d_in[12];
    float*       out   = (float*)d_out;

    const int* src = eidx;
    const int* dst = eidx + N_EDGES;

    cudaFuncSetAttribute(edge_kernel, cudaFuncAttributeMaxDynamicSharedMemorySize, EDGE_SMEM);
    cudaFuncSetAttribute(node_kernel, cudaFuncAttributeMaxDynamicSharedMemorySize, NODE_SMEM);

    ln_kernel<<<N_NODES / 8, 256>>>(nf, gamma, beta);
    edge_kernel<<<N_EDGES / 64, 256, EDGE_SMEM>>>(ef, mw1, mb1, mw2, mb2, src, dst);
    node_kernel<<<N_NODES / 64, 256, NODE_SMEM>>>(nf, aw1, ab1, aw2, ab2, out);
}

// round 12
// speedup vs baseline: 1.9415x; 1.9415x over previous
#include <cuda_runtime.h>
#include <cstdint>

// ---------------------------------------------------------------------------
// ENGNLayer on GB300: LN -> edge MLP via mma.sync tf32 + scatter -> node MLP
// N=40000, E=640000, D=128.  (tcgen05 unavailable: harness PTX target is
// compute_103 without the 'a' feature set; mma.sync tf32 is baseline sm_80+.)
// ---------------------------------------------------------------------------

#define N_NODES 40000
#define N_EDGES 640000
#define D 128
#define LN_EPS 1e-5f

// Device scratch (allocation-free rule)
__device__ float g_h[N_NODES * D];      // LayerNorm output
__device__ float g_msum[N_NODES * D];   // scatter sum
__device__ float g_cnt[N_NODES];        // scatter count
__device__ float g_w1t[128 * 384];      // msg_w1 transposed [n][k], tf32-rounded
__device__ float g_w2t[128 * 128];      // msg_w2 transposed [n][k], tf32-rounded

__device__ __forceinline__ float silu(float x) { return x / (1.0f + __expf(-x)); }

__device__ __forceinline__ uint32_t f2tf(float f) {   // unbiased fp32 -> tf32
    uint32_t r;
    asm("cvt.rna.tf32.f32 %0, %1;" : "=r"(r) : "f"(f));
    return r;
}

// m16n8k8 tf32 MMA, D += A*B (fp32 accumulate)
__device__ __forceinline__ void mma_tf32(
    float& c0, float& c1, float& c2, float& c3,
    uint32_t a0, uint32_t a1, uint32_t a2, uint32_t a3,
    uint32_t b0, uint32_t b1)
{
    asm volatile(
        "mma.sync.aligned.m16n8k8.row.col.f32.tf32.tf32.f32 "
        "{%0,%1,%2,%3}, {%4,%5,%6,%7}, {%8,%9}, {%0,%1,%2,%3};"
        : "+f"(c0), "+f"(c1), "+f"(c2), "+f"(c3)
        : "r"(a0), "r"(a1), "r"(a2), "r"(a3), "r"(b0), "r"(b1));
}

// ---------------------------------------------------------------------------
// Kernel 0: transpose + tf32-round msg weights.  W1[384][128] -> W1t[128][384].
// ---------------------------------------------------------------------------
__global__ __launch_bounds__(256) void prep_weights(
    const float* __restrict__ w1, const float* __restrict__ w2)
{
    int i = blockIdx.x * 256 + threadIdx.x;
    if (i < 384 * 128) {
        int k = i >> 7, n = i & 127;
        g_w1t[n * 384 + k] = __uint_as_float(f2tf(w1[i]));
    } else {
        int j = i - 384 * 128;
        int k = j >> 7, n = j & 127;
        g_w2t[n * 128 + k] = __uint_as_float(f2tf(w2[j]));
    }
}

// ---------------------------------------------------------------------------
// Kernel 1: LayerNorm + zero scatter buffers.
// ---------------------------------------------------------------------------
__global__ __launch_bounds__(256) void ln_kernel(
    const float* __restrict__ nf,
    const float* __restrict__ gamma,
    const float* __restrict__ beta)
{
    int node = blockIdx.x * 8 + (threadIdx.x >> 5);
    int lane = threadIdx.x & 31;
    if (node >= N_NODES) return;

    float4 v = ((const float4*)(nf + (size_t)node * D))[lane];
    float s  = v.x + v.y + v.z + v.w;
    float sq = v.x * v.x + v.y * v.y + v.z * v.z + v.w * v.w;
    #pragma unroll
    for (int off = 16; off; off >>= 1) {
        s  += __shfl_xor_sync(0xFFFFFFFFu, s, off);
        sq += __shfl_xor_sync(0xFFFFFFFFu, sq, off);
    }
    float mu = s * (1.0f / D);
    float var = sq * (1.0f / D) - mu * mu;
    float rstd = rsqrtf(var + LN_EPS);

    float4 g = ((const float4*)gamma)[lane];
    float4 b = ((const float4*)beta)[lane];
    float4 h;
    h.x = (v.x - mu) * rstd * g.x + b.x;
    h.y = (v.y - mu) * rstd * g.y + b.y;
    h.z = (v.z - mu) * rstd * g.z + b.z;
    h.w = (v.w - mu) * rstd * g.w + b.w;
    ((float4*)(g_h + (size_t)node * D))[lane] = h;
    ((float4*)(g_msum + (size_t)node * D))[lane] = make_float4(0.f, 0.f, 0.f, 0.f);
    if (lane == 0) g_cnt[node] = 0.0f;
}

// ---------------------------------------------------------------------------
// Kernel 2: edge MLP on mma.sync tf32 + scatter.
// 128 edges/block, 256 threads (8 warps). Warp w -> rows [16w,16w+16), N=128.
// SMEM rows padded to 36 floats: frag-load bank = (4*row + k) % 32, conflict-free.
// Ms: 4 k-tiles of m1 (GEMM2 A); tile 0 doubles as GEMM1's A buffer.
// ---------------------------------------------------------------------------
#define PADK 36
#define TILE_B (128 * PADK * 4)          // 18432 bytes per [128][36] tile
#define BB_OFF (4 * TILE_B)              // 73728
#define MISC   (BB_OFF + TILE_B)         // 92160
#define EDGE_SMEM (MISC + 2048)          // 94208

__global__ __launch_bounds__(256, 2) void edge_kernel(
    const float* __restrict__ ef,
    const float* __restrict__ b1,
    const float* __restrict__ b2,
    const int*  __restrict__ src,
    const int*  __restrict__ dst)
{
    extern __shared__ char smem[];
    uint32_t* Ms = (uint32_t*)smem;                 // [4][128][PADK]
    uint32_t* As = Ms;                              // alias tile 0 (GEMM1 A)
    uint32_t* Bs = (uint32_t*)(smem + BB_OFF);      // [128][PADK]
    int*   s_src = (int*)(smem + MISC);
    int*   s_dst = (int*)(smem + MISC + 512);
    float* s_b1  = (float*)(smem + MISC + 1024);
    float* s_b2  = (float*)(smem + MISC + 1536);

    const int tid  = threadIdx.x;
    const int wid  = tid >> 5;
    const int lane = tid & 31;
    const int e0   = blockIdx.x * 128;

    if (tid < 128) { s_src[tid] = src[e0 + tid];             s_b1[tid] = b1[tid]; }
    else           { s_dst[tid - 128] = dst[e0 + tid - 128]; s_b2[tid - 128] = b2[tid - 128]; }

    const int lrow  = tid >> 1;          // loader: row 0..127
    const int lhalf = tid & 1;           // which 16-float half of 32-col tile
    const int qr = lane >> 2;            // fragment quad-row 0..7
    const int qc = lane & 3;             // fragment quad-col 0..3
    const int r0 = wid * 16;             // warp's output row base

    float acc[16][4];
    #pragma unroll
    for (int nt = 0; nt < 16; ++nt)
        #pragma unroll
        for (int j = 0; j < 4; ++j) acc[nt][j] = 0.0f;

    // ---------------- GEMM1: [128 x 384] @ W1t -> m1, 12 k-tiles of 32 ------
    for (int kt = 0; kt < 12; ++kt) {
        __syncthreads();   // prior iteration's fragment reads complete

        // A tile: gather row, round to tf32, store padded
        const float* ab;
        if (kt < 4)      ab = g_h + (size_t)s_src[lrow] * D + kt * 32;
        else if (kt < 8) ab = g_h + (size_t)s_dst[lrow] * D + (kt - 4) * 32;
        else             ab = ef  + (size_t)(e0 + lrow) * D + (kt - 8) * 32;
        ab += lhalf * 16;
        uint32_t* ap = As + lrow * PADK + lhalf * 16;
        #pragma unroll
        for (int j = 0; j < 4; ++j) {
            float4 v = *(const float4*)(ab + j * 4);
            uint4 t;
            t.x = f2tf(v.x); t.y = f2tf(v.y); t.z = f2tf(v.z); t.w = f2tf(v.w);
            *(uint4*)(ap + j * 4) = t;
        }
        // B tile: pre-rounded W1t[n][k]
        const float* wb = g_w1t + lrow * 384 + kt * 32 + lhalf * 16;
        uint32_t* bp = Bs + lrow * PADK + lhalf * 16;
        #pragma unroll
        for (int j = 0; j < 4; ++j)
            *(uint4*)(bp + j * 4) = *(const uint4*)(wb + j * 4);
        __syncthreads();

        // A fragments for 4 k-steps
        uint32_t a[4][4];
        #pragma unroll
        for (int ks = 0; ks < 4; ++ks) {
            int k0 = ks * 8;
            a[ks][0] = As[(r0 + qr)     * PADK + k0 + qc];
            a[ks][1] = As[(r0 + qr + 8) * PADK + k0 + qc];
            a[ks][2] = As[(r0 + qr)     * PADK + k0 + qc + 4];
            a[ks][3] = As[(r0 + qr + 8) * PADK + k0 + qc + 4];
        }
        #pragma unroll
        for (int nt = 0; nt < 16; ++nt) {
            const uint32_t* brow = Bs + (nt * 8 + qr) * PADK;
            #pragma unroll
            for (int ks = 0; ks < 4; ++ks) {
                uint32_t b0 = brow[ks * 8 + qc];
                uint32_t b1r = brow[ks * 8 + qc + 4];
                mma_tf32(acc[nt][0], acc[nt][1], acc[nt][2], acc[nt][3],
                         a[ks][0], a[ks][1], a[ks][2], a[ks][3], b0, b1r);
            }
        }
    }

    // ---- epilogue1: bias + silu -> tf32 -> Ms k-tiles (GEMM2 A operand) ----
    __syncthreads();   // all frag reads of As/Bs done before overwriting Ms
    #pragma unroll
    for (int nt = 0; nt < 16; ++nt) {
        #pragma unroll
        for (int j = 0; j < 4; ++j) {
            int row = r0 + qr + ((j >> 1) << 3);
            int col = nt * 8 + 2 * qc + (j & 1);
            float v = silu(acc[nt][j] + s_b1[col]);
            Ms[((col >> 5) * 128 + row) * PADK + (col & 31)] = f2tf(v);
            acc[nt][j] = 0.0f;
        }
    }

    // ---------------- GEMM2: m1 [128 x 128] @ W2t, 4 k-tiles ----------------
    for (int kt = 0; kt < 4; ++kt) {
        __syncthreads();   // Ms writes visible / prior Bs reads done
        const float* wb = g_w2t + lrow * 128 + kt * 32 + lhalf * 16;
        uint32_t* bp = Bs + lrow * PADK + lhalf * 16;
        #pragma unroll
        for (int j = 0; j < 4; ++j)
            *(uint4*)(bp + j * 4) = *(const uint4*)(wb + j * 4);
        __syncthreads();

        const uint32_t* Am = Ms + kt * 128 * PADK;
        uint32_t a[4][4];
        #pragma unroll
        for (int ks = 0; ks < 4; ++ks) {
            int k0 = ks * 8;
            a[ks][0] = Am[(r0 + qr)     * PADK + k0 + qc];
            a[ks][1] = Am[(r0 + qr + 8) * PADK + k0 + qc];
            a[ks][2] = Am[(r0 + qr)     * PADK + k0 + qc + 4];
            a[ks][3] = Am[(r0 + qr + 8) * PADK + k0 + qc + 4];
        }
        #pragma unroll
        for (int nt = 0; nt < 16; ++nt) {
            const uint32_t* brow = Bs + (nt * 8 + qr) * PADK;
            #pragma unroll
            for (int ks = 0; ks < 4; ++ks) {
                uint32_t b0 = brow[ks * 8 + qc];
                uint32_t b1r = brow[ks * 8 + qc + 4];
                mma_tf32(acc[nt][0], acc[nt][1], acc[nt][2], acc[nt][3],
                         a[ks][0], a[ks][1], a[ks][2], a[ks][3], b0, b1r);
            }
        }
    }

    // ---- final epilogue: bias + silu + red.add.v2 scatter into g_msum ------
    {
        const int rA = r0 + qr, rB = rA + 8;
        const int sA = s_src[rA], sB = s_src[rB];
        float* baseA = g_msum + (size_t)sA * D;
        float* baseB = g_msum + (size_t)sB * D;
        #pragma unroll
        for (int nt = 0; nt < 16; ++nt) {
            int c0 = nt * 8 + 2 * qc;
            float v0 = silu(acc[nt][0] + s_b2[c0]);
            float v1 = silu(acc[nt][1] + s_b2[c0 + 1]);
            float v2 = silu(acc[nt][2] + s_b2[c0]);
            float v3 = silu(acc[nt][3] + s_b2[c0 + 1]);
            asm volatile("red.global.add.v2.f32 [%0], {%1,%2};"
                         :: "l"(baseA + c0), "f"(v0), "f"(v1) : "memory");
            asm volatile("red.global.add.v2.f32 [%0], {%1,%2};"
                         :: "l"(baseB + c0), "f"(v2), "f"(v3) : "memory");
        }
        if (qc == 0) {
            atomicAdd(&g_cnt[sA], 1.0f);
            atomicAdd(&g_cnt[sB], 1.0f);
        }
    }
}

// ---------------------------------------------------------------------------
// Kernel 3: node aggregation MLP + residual (SIMT fp32, ~4 GFLOP).
// ---------------------------------------------------------------------------
#define NODE_SMEM (8192 + 16384 + 32768 + 256 + 512 + 512)

__global__ __launch_bounds__(256, 3) void node_kernel(
    const float* __restrict__ nf,
    const float* __restrict__ w1,  // [256,128]
    const float* __restrict__ b1,
    const float* __restrict__ w2,  // [128,128]
    const float* __restrict__ b2,
    float* __restrict__ out)
{
    extern __shared__ char smem_raw[];
    float* As    = (float*)smem_raw;
    float* Bs    = (float*)(smem_raw + 8192);
    float* Ms    = (float*)(smem_raw + 8192 + 16384);
    float* s_inv = (float*)(smem_raw + 8192 + 16384 + 32768);
    float* s_b1  = s_inv + 64;
    float* s_b2  = s_b1 + 128;

    const int tid = threadIdx.x;
    const int n0  = blockIdx.x * 64;

    if (tid < 64) {
        float c = g_cnt[n0 + tid];
        s_inv[tid] = 1.0f / fmaxf(c, 1.0f);
    }
    if (tid < 128) s_b1[tid] = b1[tid];
    else if (tid < 256) s_b2[tid - 128] = b2[tid - 128];
    __syncthreads();

    const int tx = tid & 31;
    const int ty = tid >> 5;
    const int row0 = ty * 8;
    const int col0 = tx * 4;
    const int arow = tid >> 2;
    const int acol = (tid & 3) * 8;

    float acc[8][4];
    #pragma unroll
    for (int i = 0; i < 8; i++)
        #pragma unroll
        for (int j = 0; j < 4; j++) acc[i][j] = 0.0f;

    for (int kt = 0; kt < 8; ++kt) {
        int seg = kt >> 2;
        int kin = (kt & 3) * 32;
        const float* abase = (seg == 0 ? g_h : g_msum) + (size_t)(n0 + arow) * D;
        float4 va = *(const float4*)(abase + kin + acol);
        float4 vb = *(const float4*)(abase + kin + acol + 4);
        if (seg == 1) {
            float inv = s_inv[arow];
            va.x *= inv; va.y *= inv; va.z *= inv; va.w *= inv;
            vb.x *= inv; vb.y *= inv; vb.z *= inv; vb.w *= inv;
        }
        *(float4*)(As + arow * 32 + acol)     = va;
        *(float4*)(As + arow * 32 + acol + 4) = vb;

        const float* wbase = w1 + kt * 32 * 128;
        #pragma unroll
        for (int i = 0; i < 4; i++) {
            int idx = (tid + i * 256) * 4;
            *(float4*)(Bs + idx) = *(const float4*)(wbase + idx);
        }
        __syncthreads();

        #pragma unroll
        for (int k = 0; k < 32; k++) {
            float4 bvec = *(const float4*)(Bs + k * 128 + col0);
            float a[8];
            #pragma unroll
            for (int i = 0; i < 8; i++) a[i] = As[(row0 + i) * 32 + k];
            #pragma unroll
            for (int i = 0; i < 8; i++) {
                acc[i][0] += a[i] * bvec.x; acc[i][1] += a[i] * bvec.y;
                acc[i][2] += a[i] * bvec.z; acc[i][3] += a[i] * bvec.w;
            }
        }
        __syncthreads();
    }

    {
        float bx = s_b1[col0], by = s_b1[col0 + 1], bz = s_b1[col0 + 2], bw = s_b1[col0 + 3];
        #pragma unroll
        for (int i = 0; i < 8; i++) {
            float4 v;
            v.x = silu(acc[i][0] + bx); v.y = silu(acc[i][1] + by);
            v.z = silu(acc[i][2] + bz); v.w = silu(acc[i][3] + bw);
            *(float4*)(Ms + (row0 + i) * 128 + col0) = v;
            acc[i][0] = 0.f; acc[i][1] = 0.f; acc[i][2] = 0.f; acc[i][3] = 0.f;
        }
    }
    __syncthreads();

    for (int kt = 0; kt < 4; ++kt) {
        const float* wbase = w2 + kt * 32 * 128;
        #pragma unroll
        for (int i = 0; i < 4; i++) {
            int idx = (tid + i * 256) * 4;
            *(float4*)(Bs + idx) = *(const float4*)(wbase + idx);
        }
        __syncthreads();
        #pragma unroll
        for (int k = 0; k < 32; k++) {
            int kk = kt * 32 + k;
            float4 bvec = *(const float4*)(Bs + k * 128 + col0);
            float a[8];
            #pragma unroll
            for (int i = 0; i < 8; i++) a[i] = Ms[(row0 + i) * 128 + kk];
            #pragma unroll
            for (int i = 0; i < 8; i++) {
                acc[i][0] += a[i] * bvec.x; acc[i][1] += a[i] * bvec.y;
                acc[i][2] += a[i] * bvec.z; acc[i][3] += a[i] * bvec.w;
            }
        }
        __syncthreads();
    }

    {
        float bx = s_b2[col0], by = s_b2[col0 + 1], bz = s_b2[col0 + 2], bw = s_b2[col0 + 3];
        #pragma unroll
        for (int i = 0; i < 8; i++) {
            int node = n0 + row0 + i;
            float4 res = *(const float4*)(nf + (size_t)node * D + col0);
            float4 v;
            v.x = res.x + silu(acc[i][0] + bx);
            v.y = res.y + silu(acc[i][1] + by);
            v.z = res.z + silu(acc[i][2] + bz);
            v.w = res.w + silu(acc[i][3] + bw);
            *(float4*)(out + (size_t)node * D + col0) = v;
        }
    }
}

// ---------------------------------------------------------------------------
extern "C" void kernel_launch(void* const* d_in, const int* in_sizes, int n_in,
                              void* d_out, int out_size)
{
    const float* nf    = (const float*)d_in[0];
    const float* ef    = (const float*)d_in[1];
    const float* gamma = (const float*)d_in[2];
    const float* beta  = (const float*)d_in[3];
    const float* mw1   = (const float*)d_in[4];
    const float* mb1   = (const float*)d_in[5];
    const float* mw2   = (const float*)d_in[6];
    const float* mb2   = (const float*)d_in[7];
    const float* aw1   = (const float*)d_in[8];
    const float* ab1   = (const float*)d_in[9];
    const float* aw2   = (const float*)d_in[10];
    const float* ab2   = (const float*)d_in[11];
    const int*   eidx  = (const int*)d_in[12];
    float*       out   = (float*)d_out;

    const int* src = eidx;
    const int* dst = eidx + N_EDGES;

    cudaFuncSetAttribute(edge_kernel, cudaFuncAttributeMaxDynamicSharedMemorySize, EDGE_SMEM);
    cudaFuncSetAttribute(node_kernel, cudaFuncAttributeMaxDynamicSharedMemorySize, NODE_SMEM);

    prep_weights<<<(384 * 128 + 128 * 128) / 256, 256>>>(mw1, mw2);
    ln_kernel<<<N_NODES / 8, 256>>>(nf, gamma, beta);
    edge_kernel<<<N_EDGES / 128, 256, EDGE_SMEM>>>(ef, mb1, mb2, src, dst);
    node_kernel<<<N_NODES / 64, 256, NODE_SMEM>>>(nf, aw1, ab1, aw2, ab2, out);
}